// round 7
// baseline (speedup 1.0000x reference)
#include <cuda_runtime.h>
#include <math.h>

#define T_STEPS 32
#define N_BATCH 16
#define D_DIM   256
#define A_DIM   256
#define F1_DIM  512
#define F2_DIM  256
#define BK 16

// Scratch (allocation-free rule: __device__ globals)
__device__ float g_s2[T_STEPS * N_BATCH * D_DIM];    // [T,N,D]   512KB
__device__ float g_h1[T_STEPS * N_BATCH * F1_DIM];   // [T,N,F1]  1MB
__device__ float g_part[9 * 256 * 1024];             // split-K partials, 9MB

// ---------------------------------------------------------------------------
// K1: fused SDC-linear + exp-filter + LIF + synapse-filter + pool + s2-LIF.
// block = (n,d) (4096 blocks), 128 threads; thread owns chains a=tid, a=tid+128.
// Per-t: local 2-chain fold + 5-shfl warp reduce -> sh[t][warp(0..3)].
// ONE barrier, warp-0 epilogue (lane==t) for the scalar LIF-2 chain.
// ---------------------------------------------------------------------------
__global__ void __launch_bounds__(128) k_snn_core(
    const float* __restrict__ x,      // [T,N,2,D]
    const float* __restrict__ W_sdc,  // [2,A]
    const float* __restrict__ b_sdc,  // [A]
    const float* __restrict__ w_syn,  // [1]
    const float* __restrict__ W_pool, // [A,1]
    const float* __restrict__ b_pool) // [1]
{
    const int tid  = threadIdx.x;
    const int nd   = blockIdx.x;
    const int n    = nd >> 8;   // D = 256
    const int d    = nd & 255;
    const int lane = tid & 31;
    const int warp = tid >> 5;
    const int aA   = tid;          // chain 0
    const int aB   = tid + 128;    // chain 1

    const float w0A = W_sdc[aA],          w0B = W_sdc[aB];
    const float w1A = W_sdc[A_DIM + aA],  w1B = W_sdc[A_DIM + aB];
    const float baA = b_sdc[aA],          baB = b_sdc[aB];
    const float wpA = W_pool[aA],         wpB = W_pool[aB];
    const float dsyn = 1.0f - 1.0f / (1.0f + expf(-w_syn[0]));
    const float bp = b_pool[0];

    float isA = 0.0f, vA = 0.0f, syA = 0.0f;
    float isB = 0.0f, vB = 0.0f, syB = 0.0f;

    __shared__ float sh[T_STEPS][4];

    #pragma unroll 4
    for (int t = 0; t < T_STEPS; ++t) {
        const float x0 = x[((t * N_BATCH + n) * 2 + 0) * D_DIM + d];
        const float x1 = x[((t * N_BATCH + n) * 2 + 1) * D_DIM + d];

        // chain A
        const float hA = fmaf(x0, w0A, fmaf(x1, w1A, baA));
        isA = fmaf(isA, 0.5f, hA);
        vA  = fmaf(isA - vA, 0.5f, vA);
        const float s1A = (vA >= 1.0f) ? 1.0f : 0.0f;
        vA  = (s1A != 0.0f) ? 0.0f : vA;
        syA = fmaf(syA, dsyn, s1A);
        // chain B
        const float hB = fmaf(x0, w0B, fmaf(x1, w1B, baB));
        isB = fmaf(isB, 0.5f, hB);
        vB  = fmaf(isB - vB, 0.5f, vB);
        const float s1B = (vB >= 1.0f) ? 1.0f : 0.0f;
        vB  = (s1B != 0.0f) ? 0.0f : vB;
        syB = fmaf(syB, dsyn, s1B);

        float val = fmaf(syA, wpA, syB * wpB);
        #pragma unroll
        for (int off = 16; off; off >>= 1)
            val += __shfl_down_sync(0xffffffffu, val, off);
        if (lane == 0) sh[t][warp] = val;
    }
    __syncthreads();

    if (warp == 0) {
        // lane == t
        float z = bp + sh[lane][0] + sh[lane][1] + sh[lane][2] + sh[lane][3];

        float v2 = 0.0f, s_mine = 0.0f;
        #pragma unroll
        for (int t = 0; t < T_STEPS; ++t) {
            const float zt = __shfl_sync(0xffffffffu, z, t);
            v2 = fmaf(zt - v2, 0.5f, v2);
            const float s = (v2 >= 1.0f) ? 1.0f : 0.0f;
            v2 = (s != 0.0f) ? 0.0f : v2;
            if (lane == t) s_mine = s;
        }
        g_s2[(lane * N_BATCH + n) * D_DIM + d] = s_mine;
    }
}

// ---------------------------------------------------------------------------
// Split-K register-tiled SGEMM with global->register prefetch.
// P[s][M][N] partial = A[:,ks..ks+Kc] @ B slice. Tile 32x64, BK=16,
// 128 threads, 4x4 micro-tile. Deterministic.
// ---------------------------------------------------------------------------
__global__ void __launch_bounds__(128) k_gemm_splitk(
    const float* __restrict__ A, const float* __restrict__ B,
    float* __restrict__ P, int M, int K, int N, int Kc)
{
    __shared__ float As[BK][32];   // [k][m]
    __shared__ float Bs[BK][64];   // [k][n]
    const int tid = threadIdx.x;
    const int tx  = tid & 15;
    const int ty  = tid >> 4;
    const int row0 = blockIdx.y * 32;
    const int col0 = blockIdx.x * 64;
    const int kbeg = blockIdx.z * Kc;
    const int kend = kbeg + Kc;

    const int alr = tid >> 2;
    const int alk = (tid & 3) << 2;
    const int brr = tid >> 4;
    const int bcc = (tid & 15) << 2;

    float acc[4][4] = {};

    float4 av  = *(const float4*)(A + (row0 + alr) * K + kbeg + alk);
    float4 bv0 = *(const float4*)(B + (kbeg + brr    ) * N + col0 + bcc);
    float4 bv1 = *(const float4*)(B + (kbeg + brr + 8) * N + col0 + bcc);

    for (int k0 = kbeg; k0 < kend; k0 += BK) {
        As[alk + 0][alr] = av.x;
        As[alk + 1][alr] = av.y;
        As[alk + 2][alr] = av.z;
        As[alk + 3][alr] = av.w;
        *(float4*)(&Bs[brr][bcc])     = bv0;
        *(float4*)(&Bs[brr + 8][bcc]) = bv1;
        __syncthreads();

        const int kn = k0 + BK;
        if (kn < kend) {   // prefetch next tile while computing
            av  = *(const float4*)(A + (row0 + alr) * K + kn + alk);
            bv0 = *(const float4*)(B + (kn + brr    ) * N + col0 + bcc);
            bv1 = *(const float4*)(B + (kn + brr + 8) * N + col0 + bcc);
        }

        #pragma unroll
        for (int kk = 0; kk < BK; ++kk) {
            const float4 a = *(const float4*)(&As[kk][ty << 2]);
            const float4 b = *(const float4*)(&Bs[kk][tx << 2]);
            acc[0][0] = fmaf(a.x, b.x, acc[0][0]);
            acc[0][1] = fmaf(a.x, b.y, acc[0][1]);
            acc[0][2] = fmaf(a.x, b.z, acc[0][2]);
            acc[0][3] = fmaf(a.x, b.w, acc[0][3]);
            acc[1][0] = fmaf(a.y, b.x, acc[1][0]);
            acc[1][1] = fmaf(a.y, b.y, acc[1][1]);
            acc[1][2] = fmaf(a.y, b.z, acc[1][2]);
            acc[1][3] = fmaf(a.y, b.w, acc[1][3]);
            acc[2][0] = fmaf(a.z, b.x, acc[2][0]);
            acc[2][1] = fmaf(a.z, b.y, acc[2][1]);
            acc[2][2] = fmaf(a.z, b.z, acc[2][2]);
            acc[2][3] = fmaf(a.z, b.w, acc[2][3]);
            acc[3][0] = fmaf(a.w, b.x, acc[3][0]);
            acc[3][1] = fmaf(a.w, b.y, acc[3][1]);
            acc[3][2] = fmaf(a.w, b.z, acc[3][2]);
            acc[3][3] = fmaf(a.w, b.w, acc[3][3]);
        }
        __syncthreads();
    }

    float* Pout = P + blockIdx.z * M * N;
    #pragma unroll
    for (int i = 0; i < 4; ++i) {
        float4 o;
        o.x = acc[i][0]; o.y = acc[i][1]; o.z = acc[i][2]; o.w = acc[i][3];
        *(float4*)(Pout + (row0 + (ty << 2) + i) * N + col0 + (tx << 2)) = o;
    }
}

// ---------------------------------------------------------------------------
// Fused split-K reduce + bias + LIF scan over t.
// P[s][T*N_BATCH][F] partials -> out[T*N_BATCH][F] spikes. Deterministic.
// ---------------------------------------------------------------------------
template<int S>
__global__ void k_reduce_lif(const float* __restrict__ P,
                             const float* __restrict__ bias,
                             float* __restrict__ out, int F)
{
    const int j = blockIdx.x * blockDim.x + threadIdx.x;
    const int nb = j / F;
    const int f  = j % F;
    const int MN = T_STEPS * N_BATCH * F;
    const float b = bias[f];
    float v = 0.0f;
    #pragma unroll 4
    for (int t = 0; t < T_STEPS; ++t) {
        const int m = t * N_BATCH + nb;
        float val = b;
        #pragma unroll
        for (int s = 0; s < S; ++s) val += P[s * MN + m * F + f];
        v = fmaf(val - v, 0.5f, v);
        const float sp = (v >= 1.0f) ? 1.0f : 0.0f;
        out[m * F + f] = sp;
        v = (sp != 0.0f) ? 0.0f : v;
    }
}

// ---------------------------------------------------------------------------
// Tail: fused reduce(S) + bias + LIF + W_out dot + cumsum -> final output.
// block = nb (16 blocks), thread = f2 (256). Per-t warp reduce into sh[t][warp],
// one barrier, warp-0 cumsum epilogue. Deterministic (fixed order).
// ---------------------------------------------------------------------------
template<int S>
__global__ void __launch_bounds__(256) k_tail(
    const float* __restrict__ P,      // [S][T*N][F2] partials
    const float* __restrict__ bias,   // b_f2
    const float* __restrict__ W_out,  // [F2]
    const float* __restrict__ b_out,  // [1]
    float* __restrict__ out)          // [T,N]
{
    const int nb   = blockIdx.x;
    const int f    = threadIdx.x;
    const int lane = f & 31;
    const int warp = f >> 5;
    const int MN   = T_STEPS * N_BATCH * F2_DIM;

    const float b  = bias[f];
    const float w  = W_out[f];
    const float bo = b_out[0];

    __shared__ float sh[T_STEPS][8];
    float v = 0.0f;

    #pragma unroll 4
    for (int t = 0; t < T_STEPS; ++t) {
        const int m = t * N_BATCH + nb;
        float val = b;
        #pragma unroll
        for (int s = 0; s < S; ++s) val += P[s * MN + m * F2_DIM + f];
        v = fmaf(val - v, 0.5f, v);
        const float sp = (v >= 1.0f) ? 1.0f : 0.0f;
        v = (sp != 0.0f) ? 0.0f : v;

        float r = sp * w;
        #pragma unroll
        for (int off = 16; off; off >>= 1)
            r += __shfl_down_sync(0xffffffffu, r, off);
        if (lane == 0) sh[t][warp] = r;
    }
    __syncthreads();

    if (warp == 0) {
        float z = bo;
        #pragma unroll
        for (int w8 = 0; w8 < 8; ++w8) z += sh[lane][w8];
        float acc = 0.0f, mine = 0.0f;
        #pragma unroll
        for (int t = 0; t < T_STEPS; ++t) {
            acc += __shfl_sync(0xffffffffu, z, t);
            if (lane == t) mine = acc;
        }
        out[lane * N_BATCH + nb] = mine;
    }
}

extern "C" void kernel_launch(void* const* d_in, const int* in_sizes, int n_in,
                              void* d_out, int out_size)
{
    const float* x      = (const float*)d_in[0];
    const float* W_sdc  = (const float*)d_in[1];
    const float* b_sdc  = (const float*)d_in[2];
    const float* w_syn  = (const float*)d_in[3];
    const float* W_pool = (const float*)d_in[4];
    const float* b_pool = (const float*)d_in[5];
    const float* W_f1   = (const float*)d_in[6];
    const float* b_f1   = (const float*)d_in[7];
    const float* W_f2   = (const float*)d_in[8];
    const float* b_f2   = (const float*)d_in[9];
    const float* W_out  = (const float*)d_in[10];
    const float* b_out  = (const float*)d_in[11];
    float* out = (float*)d_out;

    float* s2 = nullptr; float* h1 = nullptr; float* part = nullptr;
    cudaGetSymbolAddress((void**)&s2, g_s2);
    cudaGetSymbolAddress((void**)&h1, g_h1);
    cudaGetSymbolAddress((void**)&part, g_part);

    const int M = T_STEPS * N_BATCH;  // 512

    // K1: fused SNN core -> g_s2 [T,N,D]
    k_snn_core<<<N_BATCH * D_DIM, 128>>>(x, W_sdc, b_sdc, w_syn, W_pool, b_pool);

    // K2: partials of s2 @ W_f1  (M=512, K=256, N=512), S=8, Kc=32 -> 1024 blocks
    {
        dim3 grid(F1_DIM / 64, M / 32, 8);
        k_gemm_splitk<<<grid, 128>>>(s2, W_f1, part, M, D_DIM, F1_DIM, 32);
    }
    // K3: reduce(8) + bias + LIF -> h1
    k_reduce_lif<8><<<(N_BATCH * F1_DIM) / 256, 256>>>(part, b_f1, h1, F1_DIM);

    // K4: partials of h1 @ W_f2  (M=512, K=512, N=256), S=16, Kc=32 -> 1024 blocks
    {
        dim3 grid(F2_DIM / 64, M / 32, 16);
        k_gemm_splitk<<<grid, 128>>>(h1, W_f2, part, M, F1_DIM, F2_DIM, 32);
    }
    // K5: fused reduce(16) + LIF + readout dot + cumsum -> out
    k_tail<16><<<N_BATCH, 256>>>(part, b_f2, W_out, b_out, out);
}

// round 8
// speedup vs baseline: 1.2862x; 1.2862x over previous
#include <cuda_runtime.h>
#include <math.h>

#define T_STEPS 32
#define N_BATCH 16
#define D_DIM   256
#define A_DIM   256
#define F1_DIM  512
#define F2_DIM  256
#define BK 16

// Scratch (allocation-free rule: __device__ globals)
__device__ float g_s2[T_STEPS * N_BATCH * D_DIM];    // [T,N,D]   512KB
__device__ float g_h1[T_STEPS * N_BATCH * F1_DIM];   // [T,N,F1]  1MB
__device__ float g_part[9 * 256 * 1024];             // split-K partials, 9MB

// ---------------------------------------------------------------------------
// K1: fused SDC-linear + exp-filter + LIF + synapse-filter + pool + s2-LIF.
// block = (n,d) (4096 blocks), thread = a (256), lane owns ONE chain (the
// measured-fast R6 shape). Per-t reduce: 3 shfls -> 4 partials -> smem.
// ONE barrier. Warp-0 epilogue: lane t sums 8 float4s, scalar LIF-2 chain.
// ---------------------------------------------------------------------------
__global__ void __launch_bounds__(256) k_snn_core(
    const float* __restrict__ x,      // [T,N,2,D]
    const float* __restrict__ W_sdc,  // [2,A]
    const float* __restrict__ b_sdc,  // [A]
    const float* __restrict__ w_syn,  // [1]
    const float* __restrict__ W_pool, // [A,1]
    const float* __restrict__ b_pool) // [1]
{
    const int a    = threadIdx.x;
    const int nd   = blockIdx.x;
    const int n    = nd >> 8;   // D = 256
    const int d    = nd & 255;
    const int lane = a & 31;
    const int warp = a >> 5;

    const float w0 = W_sdc[a];
    const float w1 = W_sdc[A_DIM + a];
    const float ba = b_sdc[a];
    const float wp = W_pool[a];
    const float dsyn = 1.0f - 1.0f / (1.0f + expf(-w_syn[0]));
    const float bp = b_pool[0];

    float i_s = 0.0f, v = 0.0f, syn = 0.0f;

    __shared__ float sh[T_STEPS][8][4];   // [t][warp][quarter] 4KB

    #pragma unroll 4
    for (int t = 0; t < T_STEPS; ++t) {
        const float x0 = x[((t * N_BATCH + n) * 2 + 0) * D_DIM + d];
        const float x1 = x[((t * N_BATCH + n) * 2 + 1) * D_DIM + d];
        const float h  = fmaf(x0, w0, fmaf(x1, w1, ba));

        i_s = fmaf(i_s, 0.5f, h);                     // exp_filter tau=2
        v = fmaf(i_s - v, 0.5f, v);                   // LIF tau=2
        const float s1 = (v >= 1.0f) ? 1.0f : 0.0f;
        v = (s1 != 0.0f) ? 0.0f : v;
        syn = fmaf(syn, dsyn, s1);                    // synapse filter

        float val = syn * wp;
        val += __shfl_down_sync(0xffffffffu, val, 16);
        val += __shfl_down_sync(0xffffffffu, val, 8);
        val += __shfl_down_sync(0xffffffffu, val, 4);
        if (lane < 4) sh[t][warp][lane] = val;        // 4 partials per warp
    }
    __syncthreads();

    if (warp == 0) {
        // lane == t : sum 32 partials (8 float4s, contiguous & 16B aligned)
        float z = bp;
        const float4* q = (const float4*)(&sh[lane][0][0]);
        #pragma unroll
        for (int w = 0; w < 8; ++w) {
            const float4 p = q[w];
            z += p.x + p.y + p.z + p.w;
        }

        float v2 = 0.0f, s_mine = 0.0f;
        #pragma unroll
        for (int t = 0; t < T_STEPS; ++t) {
            const float zt = __shfl_sync(0xffffffffu, z, t);
            v2 = fmaf(zt - v2, 0.5f, v2);
            const float s = (v2 >= 1.0f) ? 1.0f : 0.0f;
            v2 = (s != 0.0f) ? 0.0f : v2;
            if (lane == t) s_mine = s;
        }
        g_s2[(lane * N_BATCH + n) * D_DIM + d] = s_mine;
    }
}

// ---------------------------------------------------------------------------
// Split-K SGEMM, 64x64 tile, BK=16, 128 threads, 8x4 micro-tile.
// 32 FMA per 3 LDS.128 in the inner loop; global->register prefetch.
// P[s][M][N] partial = A[:,ks..ks+Kc] @ B slice. Deterministic.
// ---------------------------------------------------------------------------
__global__ void __launch_bounds__(128) k_gemm_splitk(
    const float* __restrict__ A, const float* __restrict__ B,
    float* __restrict__ P, int M, int K, int N, int Kc)
{
    __shared__ float As[BK][64];   // [k][m]
    __shared__ float Bs[BK][64];   // [k][n]
    const int tid = threadIdx.x;
    const int tx  = tid & 15;      // col group (4 cols)
    const int ty  = tid >> 4;      // row group (8 rows), 0..7
    const int row0 = blockIdx.y * 64;
    const int col0 = blockIdx.x * 64;
    const int kbeg = blockIdx.z * Kc;
    const int kend = kbeg + Kc;

    const int ar = tid >> 1;             // 0..63 : A row
    const int ak = (tid & 1) << 3;       // 0 or 8 : A k-seg
    const int bk = tid >> 3;             // 0..15 : B k row
    const int bn = (tid & 7) << 3;       // B col seg (8)

    float acc[8][4] = {};

    float4 a0 = *(const float4*)(A + (row0 + ar) * K + kbeg + ak);
    float4 a1 = *(const float4*)(A + (row0 + ar) * K + kbeg + ak + 4);
    float4 b0 = *(const float4*)(B + (kbeg + bk) * N + col0 + bn);
    float4 b1 = *(const float4*)(B + (kbeg + bk) * N + col0 + bn + 4);

    for (int k0 = kbeg; k0 < kend; k0 += BK) {
        As[ak + 0][ar] = a0.x;  As[ak + 1][ar] = a0.y;
        As[ak + 2][ar] = a0.z;  As[ak + 3][ar] = a0.w;
        As[ak + 4][ar] = a1.x;  As[ak + 5][ar] = a1.y;
        As[ak + 6][ar] = a1.z;  As[ak + 7][ar] = a1.w;
        *(float4*)(&Bs[bk][bn])     = b0;
        *(float4*)(&Bs[bk][bn + 4]) = b1;
        __syncthreads();

        const int kn = k0 + BK;
        if (kn < kend) {   // prefetch next tile while computing
            a0 = *(const float4*)(A + (row0 + ar) * K + kn + ak);
            a1 = *(const float4*)(A + (row0 + ar) * K + kn + ak + 4);
            b0 = *(const float4*)(B + (kn + bk) * N + col0 + bn);
            b1 = *(const float4*)(B + (kn + bk) * N + col0 + bn + 4);
        }

        #pragma unroll
        for (int kk = 0; kk < BK; ++kk) {
            const float4 av0 = *(const float4*)(&As[kk][ty << 3]);
            const float4 av1 = *(const float4*)(&As[kk][(ty << 3) + 4]);
            const float4 bv  = *(const float4*)(&Bs[kk][tx << 2]);
            acc[0][0] = fmaf(av0.x, bv.x, acc[0][0]);
            acc[0][1] = fmaf(av0.x, bv.y, acc[0][1]);
            acc[0][2] = fmaf(av0.x, bv.z, acc[0][2]);
            acc[0][3] = fmaf(av0.x, bv.w, acc[0][3]);
            acc[1][0] = fmaf(av0.y, bv.x, acc[1][0]);
            acc[1][1] = fmaf(av0.y, bv.y, acc[1][1]);
            acc[1][2] = fmaf(av0.y, bv.z, acc[1][2]);
            acc[1][3] = fmaf(av0.y, bv.w, acc[1][3]);
            acc[2][0] = fmaf(av0.z, bv.x, acc[2][0]);
            acc[2][1] = fmaf(av0.z, bv.y, acc[2][1]);
            acc[2][2] = fmaf(av0.z, bv.z, acc[2][2]);
            acc[2][3] = fmaf(av0.z, bv.w, acc[2][3]);
            acc[3][0] = fmaf(av0.w, bv.x, acc[3][0]);
            acc[3][1] = fmaf(av0.w, bv.y, acc[3][1]);
            acc[3][2] = fmaf(av0.w, bv.z, acc[3][2]);
            acc[3][3] = fmaf(av0.w, bv.w, acc[3][3]);
            acc[4][0] = fmaf(av1.x, bv.x, acc[4][0]);
            acc[4][1] = fmaf(av1.x, bv.y, acc[4][1]);
            acc[4][2] = fmaf(av1.x, bv.z, acc[4][2]);
            acc[4][3] = fmaf(av1.x, bv.w, acc[4][3]);
            acc[5][0] = fmaf(av1.y, bv.x, acc[5][0]);
            acc[5][1] = fmaf(av1.y, bv.y, acc[5][1]);
            acc[5][2] = fmaf(av1.y, bv.z, acc[5][2]);
            acc[5][3] = fmaf(av1.y, bv.w, acc[5][3]);
            acc[6][0] = fmaf(av1.z, bv.x, acc[6][0]);
            acc[6][1] = fmaf(av1.z, bv.y, acc[6][1]);
            acc[6][2] = fmaf(av1.z, bv.z, acc[6][2]);
            acc[6][3] = fmaf(av1.z, bv.w, acc[6][3]);
            acc[7][0] = fmaf(av1.w, bv.x, acc[7][0]);
            acc[7][1] = fmaf(av1.w, bv.y, acc[7][1]);
            acc[7][2] = fmaf(av1.w, bv.z, acc[7][2]);
            acc[7][3] = fmaf(av1.w, bv.w, acc[7][3]);
        }
        __syncthreads();
    }

    float* Pout = P + blockIdx.z * M * N;
    #pragma unroll
    for (int i = 0; i < 8; ++i) {
        float4 o;
        o.x = acc[i][0]; o.y = acc[i][1]; o.z = acc[i][2]; o.w = acc[i][3];
        *(float4*)(Pout + (row0 + (ty << 3) + i) * N + col0 + (tx << 2)) = o;
    }
}

// ---------------------------------------------------------------------------
// Fused split-K reduce + bias + LIF scan over t.
// P[s][T*N_BATCH][F] partials -> out[T*N_BATCH][F] spikes. Deterministic.
// ---------------------------------------------------------------------------
template<int S>
__global__ void k_reduce_lif(const float* __restrict__ P,
                             const float* __restrict__ bias,
                             float* __restrict__ out, int F)
{
    const int j = blockIdx.x * blockDim.x + threadIdx.x;
    const int nb = j / F;
    const int f  = j % F;
    const int MN = T_STEPS * N_BATCH * F;
    const float b = bias[f];
    float v = 0.0f;
    #pragma unroll 4
    for (int t = 0; t < T_STEPS; ++t) {
        const int m = t * N_BATCH + nb;
        float val = b;
        #pragma unroll
        for (int s = 0; s < S; ++s) val += P[s * MN + m * F + f];
        v = fmaf(val - v, 0.5f, v);
        const float sp = (v >= 1.0f) ? 1.0f : 0.0f;
        out[m * F + f] = sp;
        v = (sp != 0.0f) ? 0.0f : v;
    }
}

// ---------------------------------------------------------------------------
// Tail: fused reduce(S) + bias + LIF + W_out dot + cumsum -> final output.
// block = nb (16 blocks), thread = f2 (256). Deterministic (fixed order).
// ---------------------------------------------------------------------------
template<int S>
__global__ void __launch_bounds__(256) k_tail(
    const float* __restrict__ P,      // [S][T*N][F2] partials
    const float* __restrict__ bias,   // b_f2
    const float* __restrict__ W_out,  // [F2]
    const float* __restrict__ b_out,  // [1]
    float* __restrict__ out)          // [T,N]
{
    const int nb   = blockIdx.x;
    const int f    = threadIdx.x;
    const int lane = f & 31;
    const int warp = f >> 5;
    const int MN   = T_STEPS * N_BATCH * F2_DIM;

    const float b  = bias[f];
    const float w  = W_out[f];
    const float bo = b_out[0];

    __shared__ float sh[T_STEPS][8];
    float v = 0.0f;

    #pragma unroll 4
    for (int t = 0; t < T_STEPS; ++t) {
        const int m = t * N_BATCH + nb;
        float val = b;
        #pragma unroll
        for (int s = 0; s < S; ++s) val += P[s * MN + m * F2_DIM + f];
        v = fmaf(val - v, 0.5f, v);
        const float sp = (v >= 1.0f) ? 1.0f : 0.0f;
        v = (sp != 0.0f) ? 0.0f : v;

        float r = sp * w;
        #pragma unroll
        for (int off = 16; off; off >>= 1)
            r += __shfl_down_sync(0xffffffffu, r, off);
        if (lane == 0) sh[t][warp] = r;
    }
    __syncthreads();

    if (warp == 0) {
        float z = bo;
        #pragma unroll
        for (int w8 = 0; w8 < 8; ++w8) z += sh[lane][w8];
        float acc = 0.0f, mine = 0.0f;
        #pragma unroll
        for (int t = 0; t < T_STEPS; ++t) {
            acc += __shfl_sync(0xffffffffu, z, t);
            if (lane == t) mine = acc;
        }
        out[lane * N_BATCH + nb] = mine;
    }
}

extern "C" void kernel_launch(void* const* d_in, const int* in_sizes, int n_in,
                              void* d_out, int out_size)
{
    const float* x      = (const float*)d_in[0];
    const float* W_sdc  = (const float*)d_in[1];
    const float* b_sdc  = (const float*)d_in[2];
    const float* w_syn  = (const float*)d_in[3];
    const float* W_pool = (const float*)d_in[4];
    const float* b_pool = (const float*)d_in[5];
    const float* W_f1   = (const float*)d_in[6];
    const float* b_f1   = (const float*)d_in[7];
    const float* W_f2   = (const float*)d_in[8];
    const float* b_f2   = (const float*)d_in[9];
    const float* W_out  = (const float*)d_in[10];
    const float* b_out  = (const float*)d_in[11];
    float* out = (float*)d_out;

    float* s2 = nullptr; float* h1 = nullptr; float* part = nullptr;
    cudaGetSymbolAddress((void**)&s2, g_s2);
    cudaGetSymbolAddress((void**)&h1, g_h1);
    cudaGetSymbolAddress((void**)&part, g_part);

    const int M = T_STEPS * N_BATCH;  // 512

    // K1: fused SNN core -> g_s2 [T,N,D]
    k_snn_core<<<N_BATCH * D_DIM, 256>>>(x, W_sdc, b_sdc, w_syn, W_pool, b_pool);

    // K2: partials of s2 @ W_f1  (M=512, K=256, N=512), S=4, Kc=64 -> 256 blocks
    {
        dim3 grid(F1_DIM / 64, M / 64, 4);
        k_gemm_splitk<<<grid, 128>>>(s2, W_f1, part, M, D_DIM, F1_DIM, 64);
    }
    // K3: reduce(4) + bias + LIF -> h1
    k_reduce_lif<4><<<(N_BATCH * F1_DIM) / 256, 256>>>(part, b_f1, h1, F1_DIM);

    // K4: partials of h1 @ W_f2  (M=512, K=512, N=256), S=8, Kc=64 -> 256 blocks
    {
        dim3 grid(F2_DIM / 64, M / 64, 8);
        k_gemm_splitk<<<grid, 128>>>(h1, W_f2, part, M, F1_DIM, F2_DIM, 64);
    }
    // K5: fused reduce(8) + LIF + readout dot + cumsum -> out
    k_tail<8><<<N_BATCH, 256>>>(part, b_f2, W_out, b_out, out);
}

// round 9
// speedup vs baseline: 1.4022x; 1.0902x over previous
#include <cuda_runtime.h>
#include <math.h>

#define T_STEPS 32
#define N_BATCH 16
#define D_DIM   256
#define A_DIM   256
#define F1_DIM  512
#define F2_DIM  256
#define BK 16

// Scratch (allocation-free rule: __device__ globals)
__device__ float g_s2[T_STEPS * N_BATCH * D_DIM];    // [T,N,D]   512KB
__device__ float g_h1[T_STEPS * N_BATCH * F1_DIM];   // [T,N,F1]  1MB
__device__ float g_part[9 * 256 * 1024];             // split-K partials, 9MB

// ---------------------------------------------------------------------------
// K1: fused SDC-linear + exp-filter + LIF + synapse-filter + pool + s2-LIF.
// block = (n,d) (4096 blocks), thread = a (256), lane owns ONE chain.
// Per-t reduce: ONE shfl -> 16 partials -> smem row (stride 137, coprime to
// 32 -> conflict-free store AND epilogue read). ONE barrier.
// Warp-0 epilogue: lane t sums 128 partials, scalar LIF-2 chain via shfl.
// ---------------------------------------------------------------------------
__global__ void __launch_bounds__(256) k_snn_core(
    const float* __restrict__ x,      // [T,N,2,D]
    const float* __restrict__ W_sdc,  // [2,A]
    const float* __restrict__ b_sdc,  // [A]
    const float* __restrict__ w_syn,  // [1]
    const float* __restrict__ W_pool, // [A,1]
    const float* __restrict__ b_pool) // [1]
{
    const int a    = threadIdx.x;
    const int nd   = blockIdx.x;
    const int n    = nd >> 8;   // D = 256
    const int d    = nd & 255;
    const int lane = a & 31;
    const int warp = a >> 5;

    const float w0 = W_sdc[a];
    const float w1 = W_sdc[A_DIM + a];
    const float ba = b_sdc[a];
    const float wp = W_pool[a];
    const float dsyn = 1.0f - 1.0f / (1.0f + expf(-w_syn[0]));
    const float bp = b_pool[0];

    float i_s = 0.0f, v = 0.0f, syn = 0.0f;

    __shared__ float sh[T_STEPS][137];   // stride 137: conflict-free both phases

    #pragma unroll 4
    for (int t = 0; t < T_STEPS; ++t) {
        const float x0 = x[((t * N_BATCH + n) * 2 + 0) * D_DIM + d];
        const float x1 = x[((t * N_BATCH + n) * 2 + 1) * D_DIM + d];
        const float h  = fmaf(x0, w0, fmaf(x1, w1, ba));

        i_s = fmaf(i_s, 0.5f, h);                     // exp_filter tau=2
        v = fmaf(i_s - v, 0.5f, v);                   // LIF tau=2
        const float s1 = (v >= 1.0f) ? 1.0f : 0.0f;
        v = (s1 != 0.0f) ? 0.0f : v;
        syn = fmaf(syn, dsyn, s1);                    // synapse filter

        float val = syn * wp;
        val += __shfl_down_sync(0xffffffffu, val, 16);
        if (lane < 16) sh[t][(warp << 4) + lane] = val;   // 16 partials/warp
    }
    __syncthreads();

    if (warp == 0) {
        // lane == t : sum 128 partials with 4-way ILP
        float z0 = 0.0f, z1 = 0.0f, z2 = 0.0f, z3 = 0.0f;
        #pragma unroll
        for (int j = 0; j < 128; j += 4) {
            z0 += sh[lane][j + 0];
            z1 += sh[lane][j + 1];
            z2 += sh[lane][j + 2];
            z3 += sh[lane][j + 3];
        }
        float z = bp + ((z0 + z1) + (z2 + z3));

        float v2 = 0.0f, s_mine = 0.0f;
        #pragma unroll
        for (int t = 0; t < T_STEPS; ++t) {
            const float zt = __shfl_sync(0xffffffffu, z, t);
            v2 = fmaf(zt - v2, 0.5f, v2);
            const float s = (v2 >= 1.0f) ? 1.0f : 0.0f;
            v2 = (s != 0.0f) ? 0.0f : v2;
            if (lane == t) s_mine = s;
        }
        g_s2[(lane * N_BATCH + n) * D_DIM + d] = s_mine;
    }
}

// ---------------------------------------------------------------------------
// Split-K SGEMM, 64x64 tile, BK=16, 256 THREADS (8 warps = 2/SMSP so the
// rt_SMSP=2 FMA slots can be filled), 4x4 micro-tile, global->reg prefetch.
// P[s][M][N] partial = A[:,ks..ks+Kc] @ B slice. Deterministic.
// ---------------------------------------------------------------------------
__global__ void __launch_bounds__(256) k_gemm_splitk(
    const float* __restrict__ A, const float* __restrict__ B,
    float* __restrict__ P, int M, int K, int N, int Kc)
{
    __shared__ float As[BK][68];   // [k][m], pad 4 (68*4B=272B, 16B-aligned rows)
    __shared__ float Bs[BK][64];   // [k][n]
    const int tid = threadIdx.x;
    const int tx  = tid & 15;      // col group (4 cols)
    const int ty  = tid >> 4;      // row group (4 rows), 0..15
    const int row0 = blockIdx.y * 64;
    const int col0 = blockIdx.x * 64;
    const int kbeg = blockIdx.z * Kc;
    const int kend = kbeg + Kc;

    const int ar = tid >> 2;             // 0..63 : A row
    const int ak = (tid & 3) << 2;       // 0,4,8,12 : A k-seg
    const int bk = tid >> 4;             // 0..15 : B k row
    const int bn = (tid & 15) << 2;      // B col seg (4)

    float acc[4][4] = {};

    float4 av = *(const float4*)(A + (row0 + ar) * K + kbeg + ak);
    float4 bv = *(const float4*)(B + (kbeg + bk) * N + col0 + bn);

    for (int k0 = kbeg; k0 < kend; k0 += BK) {
        As[ak + 0][ar] = av.x;
        As[ak + 1][ar] = av.y;
        As[ak + 2][ar] = av.z;
        As[ak + 3][ar] = av.w;
        *(float4*)(&Bs[bk][bn]) = bv;
        __syncthreads();

        const int kn = k0 + BK;
        if (kn < kend) {   // prefetch next tile while computing
            av = *(const float4*)(A + (row0 + ar) * K + kn + ak);
            bv = *(const float4*)(B + (kn + bk) * N + col0 + bn);
        }

        #pragma unroll
        for (int kk = 0; kk < BK; ++kk) {
            const float4 a = *(const float4*)(&As[kk][ty << 2]);
            const float4 b = *(const float4*)(&Bs[kk][tx << 2]);
            acc[0][0] = fmaf(a.x, b.x, acc[0][0]);
            acc[0][1] = fmaf(a.x, b.y, acc[0][1]);
            acc[0][2] = fmaf(a.x, b.z, acc[0][2]);
            acc[0][3] = fmaf(a.x, b.w, acc[0][3]);
            acc[1][0] = fmaf(a.y, b.x, acc[1][0]);
            acc[1][1] = fmaf(a.y, b.y, acc[1][1]);
            acc[1][2] = fmaf(a.y, b.z, acc[1][2]);
            acc[1][3] = fmaf(a.y, b.w, acc[1][3]);
            acc[2][0] = fmaf(a.z, b.x, acc[2][0]);
            acc[2][1] = fmaf(a.z, b.y, acc[2][1]);
            acc[2][2] = fmaf(a.z, b.z, acc[2][2]);
            acc[2][3] = fmaf(a.z, b.w, acc[2][3]);
            acc[3][0] = fmaf(a.w, b.x, acc[3][0]);
            acc[3][1] = fmaf(a.w, b.y, acc[3][1]);
            acc[3][2] = fmaf(a.w, b.z, acc[3][2]);
            acc[3][3] = fmaf(a.w, b.w, acc[3][3]);
        }
        __syncthreads();
    }

    float* Pout = P + blockIdx.z * M * N;
    #pragma unroll
    for (int i = 0; i < 4; ++i) {
        float4 o;
        o.x = acc[i][0]; o.y = acc[i][1]; o.z = acc[i][2]; o.w = acc[i][3];
        *(float4*)(Pout + (row0 + (ty << 2) + i) * N + col0 + (tx << 2)) = o;
    }
}

// ---------------------------------------------------------------------------
// Fused split-K reduce + bias + LIF scan over t.
// P[s][T*N_BATCH][F] partials -> out[T*N_BATCH][F] spikes. Deterministic.
// ---------------------------------------------------------------------------
template<int S>
__global__ void k_reduce_lif(const float* __restrict__ P,
                             const float* __restrict__ bias,
                             float* __restrict__ out, int F)
{
    const int j = blockIdx.x * blockDim.x + threadIdx.x;
    const int nb = j / F;
    const int f  = j % F;
    const int MN = T_STEPS * N_BATCH * F;
    const float b = bias[f];
    float v = 0.0f;
    #pragma unroll 4
    for (int t = 0; t < T_STEPS; ++t) {
        const int m = t * N_BATCH + nb;
        float val = b;
        #pragma unroll
        for (int s = 0; s < S; ++s) val += P[s * MN + m * F + f];
        v = fmaf(val - v, 0.5f, v);
        const float sp = (v >= 1.0f) ? 1.0f : 0.0f;
        out[m * F + f] = sp;
        v = (sp != 0.0f) ? 0.0f : v;
    }
}

// ---------------------------------------------------------------------------
// Tail: fused reduce(S) + bias + LIF + W_out dot + cumsum -> final output.
// block = nb (16 blocks), thread = f2 (256). Deterministic (fixed order).
// ---------------------------------------------------------------------------
template<int S>
__global__ void __launch_bounds__(256) k_tail(
    const float* __restrict__ P,      // [S][T*N][F2] partials
    const float* __restrict__ bias,   // b_f2
    const float* __restrict__ W_out,  // [F2]
    const float* __restrict__ b_out,  // [1]
    float* __restrict__ out)          // [T,N]
{
    const int nb   = blockIdx.x;
    const int f    = threadIdx.x;
    const int lane = f & 31;
    const int warp = f >> 5;
    const int MN   = T_STEPS * N_BATCH * F2_DIM;

    const float b  = bias[f];
    const float w  = W_out[f];
    const float bo = b_out[0];

    __shared__ float sh[T_STEPS][8];
    float v = 0.0f;

    #pragma unroll 4
    for (int t = 0; t < T_STEPS; ++t) {
        const int m = t * N_BATCH + nb;
        float val = b;
        #pragma unroll
        for (int s = 0; s < S; ++s) val += P[s * MN + m * F2_DIM + f];
        v = fmaf(val - v, 0.5f, v);
        const float sp = (v >= 1.0f) ? 1.0f : 0.0f;
        v = (sp != 0.0f) ? 0.0f : v;

        float r = sp * w;
        #pragma unroll
        for (int off = 16; off; off >>= 1)
            r += __shfl_down_sync(0xffffffffu, r, off);
        if (lane == 0) sh[t][warp] = r;
    }
    __syncthreads();

    if (warp == 0) {
        float z = bo;
        #pragma unroll
        for (int w8 = 0; w8 < 8; ++w8) z += sh[lane][w8];
        float acc = 0.0f, mine = 0.0f;
        #pragma unroll
        for (int t = 0; t < T_STEPS; ++t) {
            acc += __shfl_sync(0xffffffffu, z, t);
            if (lane == t) mine = acc;
        }
        out[lane * N_BATCH + nb] = mine;
    }
}

extern "C" void kernel_launch(void* const* d_in, const int* in_sizes, int n_in,
                              void* d_out, int out_size)
{
    const float* x      = (const float*)d_in[0];
    const float* W_sdc  = (const float*)d_in[1];
    const float* b_sdc  = (const float*)d_in[2];
    const float* w_syn  = (const float*)d_in[3];
    const float* W_pool = (const float*)d_in[4];
    const float* b_pool = (const float*)d_in[5];
    const float* W_f1   = (const float*)d_in[6];
    const float* b_f1   = (const float*)d_in[7];
    const float* W_f2   = (const float*)d_in[8];
    const float* b_f2   = (const float*)d_in[9];
    const float* W_out  = (const float*)d_in[10];
    const float* b_out  = (const float*)d_in[11];
    float* out = (float*)d_out;

    float* s2 = nullptr; float* h1 = nullptr; float* part = nullptr;
    cudaGetSymbolAddress((void**)&s2, g_s2);
    cudaGetSymbolAddress((void**)&h1, g_h1);
    cudaGetSymbolAddress((void**)&part, g_part);

    const int M = T_STEPS * N_BATCH;  // 512

    // K1: fused SNN core -> g_s2 [T,N,D]
    k_snn_core<<<N_BATCH * D_DIM, 256>>>(x, W_sdc, b_sdc, w_syn, W_pool, b_pool);

    // K2: partials of s2 @ W_f1  (M=512, K=256, N=512), S=4, Kc=64 -> 256 blocks
    {
        dim3 grid(F1_DIM / 64, M / 64, 4);
        k_gemm_splitk<<<grid, 256>>>(s2, W_f1, part, M, D_DIM, F1_DIM, 64);
    }
    // K3: reduce(4) + bias + LIF -> h1
    k_reduce_lif<4><<<(N_BATCH * F1_DIM) / 256, 256>>>(part, b_f1, h1, F1_DIM);

    // K4: partials of h1 @ W_f2  (M=512, K=512, N=256), S=8, Kc=64 -> 256 blocks
    {
        dim3 grid(F2_DIM / 64, M / 64, 8);
        k_gemm_splitk<<<grid, 256>>>(h1, W_f2, part, M, F1_DIM, F2_DIM, 64);
    }
    // K5: fused reduce(8) + LIF + readout dot + cumsum -> out
    k_tail<8><<<N_BATCH, 256>>>(part, b_f2, W_out, b_out, out);
}